// round 2
// baseline (speedup 1.0000x reference)
#include <cuda_runtime.h>
#include <cstdint>

#define Bn 16
#define Cn 256
#define Hn 96
#define Wn 96
#define HWc 9216
#define CHWc 2359296   // Cn*HWc
#define TOTc 37748736  // Bn*CHWc

// ---------------- scratch (static device globals: no allocations allowed) ----------------
__device__ float g_xp[TOTc];    // in_w @ x (pre-norm)
__device__ float g_gate[TOTc];  // sigmoid(gate_w @ xp_n + gate_b)
__device__ float g_sw[TOTc];    // lr + rl
__device__ float g_sh[TOTc];    // tb + bt
__device__ float g_fd[TOTc];    // depthwise conv output
__device__ float g_o1[TOTc];    // pw_w @ g_fd (pre-norm)
__device__ float g_ss1[Bn*Cn*2];  // per-(b,c) GN1 scale/shift
__device__ float g_ss2[Bn*Cn*2];  // per-(b,c) GN2 scale/shift

__device__ __forceinline__ float sigmoid_f(float x) { return 1.0f / (1.0f + __expf(-x)); }
__device__ __forceinline__ float silu_f(float x)    { return x / (1.0f + __expf(-x)); }

// ---------------- fp32 SGEMM: C[m,n] = sum_k A[m,k]*B[k,n], per-batch B/C ----------------
// M=256, N=9216, K=256. BM=BN=128, BK=8, 256 threads, 8x8 per thread.
__global__ __launch_bounds__(256) void sgemm_kernel(const float* __restrict__ A,
                                                    const float* __restrict__ Bsrc,
                                                    float* __restrict__ Cd)
{
    __shared__ float As[8][128];
    __shared__ float Bs[8][128];
    const int tid = threadIdx.x;
    const int bnn = blockIdx.x * 128;
    const int bm  = blockIdx.y * 128;
    const int bb  = blockIdx.z;
    const float* Bp = Bsrc + (size_t)bb * CHWc + bnn;
    float*       Cp = Cd   + (size_t)bb * CHWc + (size_t)bm * HWc + bnn;
    const float* Ap = A + bm * Cn;

    const int arow = tid >> 1,  acol = (tid & 1) * 4;
    const int brow = tid >> 5,  bcol = (tid & 31) * 4;
    const int tx = (tid & 15) * 8;
    const int ty = (tid >> 4) * 8;

    float acc[8][8];
#pragma unroll
    for (int i = 0; i < 8; i++)
#pragma unroll
        for (int j = 0; j < 8; j++) acc[i][j] = 0.0f;

    for (int k0 = 0; k0 < Cn; k0 += 8) {
        float4 av = *(const float4*)(Ap + arow * Cn + k0 + acol);
        float4 bv = *(const float4*)(Bp + (size_t)(k0 + brow) * HWc + bcol);
        As[acol + 0][arow] = av.x; As[acol + 1][arow] = av.y;
        As[acol + 2][arow] = av.z; As[acol + 3][arow] = av.w;
        *(float4*)&Bs[brow][bcol] = bv;
        __syncthreads();
#pragma unroll
        for (int kk = 0; kk < 8; kk++) {
            float ar[8], br[8];
            *(float4*)&ar[0] = *(const float4*)&As[kk][ty];
            *(float4*)&ar[4] = *(const float4*)&As[kk][ty + 4];
            *(float4*)&br[0] = *(const float4*)&Bs[kk][tx];
            *(float4*)&br[4] = *(const float4*)&Bs[kk][tx + 4];
#pragma unroll
            for (int i = 0; i < 8; i++)
#pragma unroll
                for (int j = 0; j < 8; j++)
                    acc[i][j] = fmaf(ar[i], br[j], acc[i][j]);
        }
        __syncthreads();
    }
#pragma unroll
    for (int i = 0; i < 8; i++) {
        *(float4*)(Cp + (size_t)(ty + i) * HWc + tx)     = make_float4(acc[i][0], acc[i][1], acc[i][2], acc[i][3]);
        *(float4*)(Cp + (size_t)(ty + i) * HWc + tx + 4) = make_float4(acc[i][4], acc[i][5], acc[i][6], acc[i][7]);
    }
}

// ---------------- gate GEMM: B operand = silu(affine(g_xp)), epilogue sigmoid(+bias) ----------------
__global__ __launch_bounds__(256) void gemm_gate_kernel(const float* __restrict__ A,
                                                        const float* __restrict__ gate_b)
{
    __shared__ float As[8][128];
    __shared__ float Bs[8][128];
    const int tid = threadIdx.x;
    const int bnn = blockIdx.x * 128;
    const int bm  = blockIdx.y * 128;
    const int bb  = blockIdx.z;
    const float* Bp = g_xp   + (size_t)bb * CHWc + bnn;
    float*       Cp = g_gate + (size_t)bb * CHWc + (size_t)bm * HWc + bnn;
    const float* Ap = A + bm * Cn;

    const int arow = tid >> 1,  acol = (tid & 1) * 4;
    const int brow = tid >> 5,  bcol = (tid & 31) * 4;
    const int tx = (tid & 15) * 8;
    const int ty = (tid >> 4) * 8;

    float acc[8][8];
#pragma unroll
    for (int i = 0; i < 8; i++)
#pragma unroll
        for (int j = 0; j < 8; j++) acc[i][j] = 0.0f;

    for (int k0 = 0; k0 < Cn; k0 += 8) {
        float4 av = *(const float4*)(Ap + arow * Cn + k0 + acol);
        const int kg = k0 + brow;
        float2 sc = *(const float2*)&g_ss1[(bb * Cn + kg) * 2];
        float4 bv = *(const float4*)(Bp + (size_t)kg * HWc + bcol);
        bv.x = silu_f(fmaf(bv.x, sc.x, sc.y));
        bv.y = silu_f(fmaf(bv.y, sc.x, sc.y));
        bv.z = silu_f(fmaf(bv.z, sc.x, sc.y));
        bv.w = silu_f(fmaf(bv.w, sc.x, sc.y));
        As[acol + 0][arow] = av.x; As[acol + 1][arow] = av.y;
        As[acol + 2][arow] = av.z; As[acol + 3][arow] = av.w;
        *(float4*)&Bs[brow][bcol] = bv;
        __syncthreads();
#pragma unroll
        for (int kk = 0; kk < 8; kk++) {
            float ar[8], br[8];
            *(float4*)&ar[0] = *(const float4*)&As[kk][ty];
            *(float4*)&ar[4] = *(const float4*)&As[kk][ty + 4];
            *(float4*)&br[0] = *(const float4*)&Bs[kk][tx];
            *(float4*)&br[4] = *(const float4*)&Bs[kk][tx + 4];
#pragma unroll
            for (int i = 0; i < 8; i++)
#pragma unroll
                for (int j = 0; j < 8; j++)
                    acc[i][j] = fmaf(ar[i], br[j], acc[i][j]);
        }
        __syncthreads();
    }
#pragma unroll
    for (int i = 0; i < 8; i++) {
        float gb = gate_b[bm + ty + i];
        float4 v0, v1;
        v0.x = sigmoid_f(acc[i][0] + gb); v0.y = sigmoid_f(acc[i][1] + gb);
        v0.z = sigmoid_f(acc[i][2] + gb); v0.w = sigmoid_f(acc[i][3] + gb);
        v1.x = sigmoid_f(acc[i][4] + gb); v1.y = sigmoid_f(acc[i][5] + gb);
        v1.z = sigmoid_f(acc[i][6] + gb); v1.w = sigmoid_f(acc[i][7] + gb);
        *(float4*)(Cp + (size_t)(ty + i) * HWc + tx)     = v0;
        *(float4*)(Cp + (size_t)(ty + i) * HWc + tx + 4) = v1;
    }
}

// ---------------- GroupNorm stats -> per-(b,c) affine (scale, shift) ----------------
// grid (16 groups, Bn batches), 256 threads. Group block is 16*HWc contiguous floats.
__global__ __launch_bounds__(256) void gn_stats_kernel(const float* __restrict__ src,
                                                       const float* __restrict__ gamma,
                                                       const float* __restrict__ beta,
                                                       float* __restrict__ ss)
{
    const int g = blockIdx.x, b = blockIdx.y, tid = threadIdx.x;
    const float4* p = (const float4*)(src + (size_t)b * CHWc + (size_t)g * 16 * HWc);
    float s = 0.0f, s2 = 0.0f;
    const int n4 = 16 * HWc / 4;
    for (int i = tid; i < n4; i += 256) {
        float4 v = p[i];
        s  += v.x + v.y + v.z + v.w;
        s2 += v.x * v.x + v.y * v.y + v.z * v.z + v.w * v.w;
    }
#pragma unroll
    for (int off = 16; off > 0; off >>= 1) {
        s  += __shfl_xor_sync(0xffffffffu, s, off);
        s2 += __shfl_xor_sync(0xffffffffu, s2, off);
    }
    __shared__ float ws[8], ws2[8];
    __shared__ float mean_s, rstd_s;
    const int wid = tid >> 5, lane = tid & 31;
    if (lane == 0) { ws[wid] = s; ws2[wid] = s2; }
    __syncthreads();
    if (tid == 0) {
        float ts = 0.0f, ts2 = 0.0f;
        for (int i = 0; i < 8; i++) { ts += ws[i]; ts2 += ws2[i]; }
        const float inv = 1.0f / (16.0f * HWc);
        float mu  = ts * inv;
        float var = ts2 * inv - mu * mu;
        mean_s = mu;
        rstd_s = rsqrtf(var + 1e-5f);
    }
    __syncthreads();
    if (tid < 16) {
        int c = g * 16 + tid;
        float sc = rstd_s * gamma[c];
        ss[(b * Cn + c) * 2 + 0] = sc;
        ss[(b * Cn + c) * 2 + 1] = beta[c] - mean_s * sc;
    }
}

// ---------------- horizontal scans (lr + rl) ----------------
// grid (Hn, Bn), 256 threads = 1 thread per channel. Dynamic smem 2*256*97*4.
#define SW_PITCH 97
__global__ __launch_bounds__(256) void scan_w_kernel(const float* __restrict__ ap,
                                                     const float* __restrict__ bp,
                                                     const float* __restrict__ cp,
                                                     const float* __restrict__ dp)
{
    extern __shared__ float sm[];
    float* xin  = sm;
    float* yout = sm + Cn * SW_PITCH;
    const int h = blockIdx.x, b = blockIdx.y, tid = threadIdx.x;
    const size_t base = (size_t)b * CHWc + (size_t)h * Wn;

    for (int i = tid; i < Cn * Wn; i += 256) {
        int c = i / Wn, w = i - c * Wn;
        float v = g_xp[base + (size_t)c * HWc + w];
        float2 sc = *(const float2*)&g_ss1[(b * Cn + c) * 2];
        xin[c * SW_PITCH + w] = silu_f(fmaf(v, sc.x, sc.y));
    }
    __syncthreads();

    const int c = tid;
    const float a0 = sigmoid_f(ap[c]),      b0 = bp[c],      c0 = cp[c],      d0 = dp[c];
    const float a1 = sigmoid_f(ap[Cn + c]), b1 = bp[Cn + c], c1 = cp[Cn + c], d1 = dp[Cn + c];
    float* xr = xin  + c * SW_PITCH;
    float* yr = yout + c * SW_PITCH;
    float hs = 0.0f;
#pragma unroll 4
    for (int w = 0; w < Wn; w++) {
        float xv = xr[w];
        hs = fmaf(a0, hs, b0 * xv);
        yr[w] = fmaf(c0, hs, d0 * xv);
    }
    hs = 0.0f;
#pragma unroll 4
    for (int w = Wn - 1; w >= 0; w--) {
        float xv = xr[w];
        hs = fmaf(a1, hs, b1 * xv);
        yr[w] += fmaf(c1, hs, d1 * xv);
    }
    __syncthreads();

    for (int i = tid; i < Cn * Wn; i += 256) {
        int cc = i / Wn, w = i - cc * Wn;
        g_sw[base + (size_t)cc * HWc + w] = yout[cc * SW_PITCH + w];
    }
}

// ---------------- vertical scans (tb + bt) ----------------
// grid (Wn/32, Cn/4, Bn), 128 threads: warp = 1 channel, lane = column. smem 2*4*96*33*4.
#define SH_PITCH 33
__global__ __launch_bounds__(128) void scan_h_kernel(const float* __restrict__ ap,
                                                     const float* __restrict__ bp,
                                                     const float* __restrict__ cp,
                                                     const float* __restrict__ dp)
{
    extern __shared__ float sm2[];
    float* xin  = sm2;
    float* yout = sm2 + 4 * Hn * SH_PITCH;
    const int b = blockIdx.z, c0 = blockIdx.y * 4, w0 = blockIdx.x * 32;
    const int tid = threadIdx.x;

    for (int i = tid; i < 4 * Hn * 32; i += 128) {
        int w = i & 31; int t = i >> 5; int hh = t % Hn; int cl = t / Hn;
        int c = c0 + cl;
        float v = g_xp[(size_t)b * CHWc + (size_t)c * HWc + hh * Wn + w0 + w];
        float2 sc = *(const float2*)&g_ss1[(b * Cn + c) * 2];
        xin[(cl * Hn + hh) * SH_PITCH + w] = silu_f(fmaf(v, sc.x, sc.y));
    }
    __syncthreads();

    const int cl = tid >> 5, w = tid & 31;
    const int c = c0 + cl;
    const float a2 = sigmoid_f(ap[2 * Cn + c]), b2 = bp[2 * Cn + c], c2 = cp[2 * Cn + c], d2 = dp[2 * Cn + c];
    const float a3 = sigmoid_f(ap[3 * Cn + c]), b3 = bp[3 * Cn + c], c3 = cp[3 * Cn + c], d3 = dp[3 * Cn + c];
    float* xc = xin  + cl * Hn * SH_PITCH + w;
    float* yc = yout + cl * Hn * SH_PITCH + w;
    float hs = 0.0f;
#pragma unroll 4
    for (int hh = 0; hh < Hn; hh++) {
        float xv = xc[hh * SH_PITCH];
        hs = fmaf(a2, hs, b2 * xv);
        yc[hh * SH_PITCH] = fmaf(c2, hs, d2 * xv);
    }
    hs = 0.0f;
#pragma unroll 4
    for (int hh = Hn - 1; hh >= 0; hh--) {
        float xv = xc[hh * SH_PITCH];
        hs = fmaf(a3, hs, b3 * xv);
        yc[hh * SH_PITCH] += fmaf(c3, hs, d3 * xv);
    }
    __syncthreads();

    for (int i = tid; i < 4 * Hn * 32; i += 128) {
        int ww = i & 31; int t = i >> 5; int hh = t % Hn; int cl2 = t / Hn;
        g_sh[(size_t)b * CHWc + (size_t)(c0 + cl2) * HWc + hh * Wn + w0 + ww] =
            yout[(cl2 * Hn + hh) * SH_PITCH + ww];
    }
}

// ---------------- fused = 0.25*(sw+sh)*gate, then 3x3 depthwise SAME conv ----------------
// grid (3, 3, Bn*Cn), 256 threads; 32x32 output tile with 34x34 halo.
__global__ __launch_bounds__(256) void fuse_dw_kernel(const float* __restrict__ dww)
{
    __shared__ float ft[34 * 36];
    const int bc = blockIdx.z;
    const int h0 = blockIdx.y * 32, w0 = blockIdx.x * 32;
    const int c = bc & (Cn - 1);
    const size_t base = (size_t)bc * HWc;
    const int tid = threadIdx.x;

    for (int i = tid; i < 34 * 34; i += 256) {
        int r = i / 34, cc = i - r * 34;
        int gh = h0 - 1 + r, gw = w0 - 1 + cc;
        float v = 0.0f;
        if ((unsigned)gh < (unsigned)Hn && (unsigned)gw < (unsigned)Wn) {
            size_t idx = base + gh * Wn + gw;
            v = 0.25f * (g_sw[idx] + g_sh[idx]) * g_gate[idx];
        }
        ft[r * 36 + cc] = v;
    }
    float kw[9];
#pragma unroll
    for (int j = 0; j < 9; j++) kw[j] = dww[c * 9 + j];
    __syncthreads();

    const int tx = tid & 31, ty0 = tid >> 5;
#pragma unroll
    for (int rr = 0; rr < 4; rr++) {
        int r = ty0 + rr * 8;
        float acc = 0.0f;
#pragma unroll
        for (int i = 0; i < 3; i++)
#pragma unroll
            for (int j = 0; j < 3; j++)
                acc = fmaf(ft[(r + i) * 36 + tx + j], kw[i * 3 + j], acc);
        g_fd[base + (size_t)(h0 + r) * Wn + w0 + tx] = acc;
    }
}

// ---------------- final: silu(affine(o1)) -> out ----------------
__global__ __launch_bounds__(256) void finalize_kernel(const float* __restrict__ src,
                                                       const float* __restrict__ ss,
                                                       float* __restrict__ out)
{
    int i4 = blockIdx.x * 256 + threadIdx.x;
    if (i4 >= TOTc / 4) return;
    int bc = i4 / (HWc / 4);
    float2 sc = *(const float2*)&ss[bc * 2];
    float4 v = ((const float4*)src)[i4];
    v.x = silu_f(fmaf(v.x, sc.x, sc.y));
    v.y = silu_f(fmaf(v.y, sc.x, sc.y));
    v.z = silu_f(fmaf(v.z, sc.x, sc.y));
    v.w = silu_f(fmaf(v.w, sc.x, sc.y));
    ((float4*)out)[i4] = v;
}

// ---------------- launch ----------------
extern "C" void kernel_launch(void* const* d_in, const int* in_sizes, int n_in,
                              void* d_out, int out_size)
{
    const float* x      = (const float*)d_in[0];
    const float* in_w   = (const float*)d_in[1];
    const float* gn1_w  = (const float*)d_in[2];
    const float* gn1_b  = (const float*)d_in[3];
    const float* a_p    = (const float*)d_in[4];
    const float* b_p    = (const float*)d_in[5];
    const float* c_p    = (const float*)d_in[6];
    const float* d_p    = (const float*)d_in[7];
    const float* gate_w = (const float*)d_in[8];
    const float* gate_b = (const float*)d_in[9];
    const float* dw_w   = (const float*)d_in[10];
    const float* pw_w   = (const float*)d_in[11];
    const float* gn2_w  = (const float*)d_in[12];
    const float* gn2_b  = (const float*)d_in[13];
    float* out = (float*)d_out;

    float *p_xp, *p_fd, *p_o1, *p_ss1, *p_ss2;
    cudaGetSymbolAddress((void**)&p_xp,  g_xp);
    cudaGetSymbolAddress((void**)&p_fd,  g_fd);
    cudaGetSymbolAddress((void**)&p_o1,  g_o1);
    cudaGetSymbolAddress((void**)&p_ss1, g_ss1);
    cudaGetSymbolAddress((void**)&p_ss2, g_ss2);

    const int smw = 2 * Cn * SW_PITCH * 4;
    const int smh = 2 * 4 * Hn * SH_PITCH * 4;
    cudaFuncSetAttribute(scan_w_kernel, cudaFuncAttributeMaxDynamicSharedMemorySize, smw);
    cudaFuncSetAttribute(scan_h_kernel, cudaFuncAttributeMaxDynamicSharedMemorySize, smh);

    dim3 gg(HWc / 128, Cn / 128, Bn);

    sgemm_kernel<<<gg, 256>>>(in_w, x, p_xp);
    gn_stats_kernel<<<dim3(16, Bn), 256>>>(p_xp, gn1_w, gn1_b, p_ss1);
    gemm_gate_kernel<<<gg, 256>>>(gate_w, gate_b);
    scan_w_kernel<<<dim3(Hn, Bn), 256, smw>>>(a_p, b_p, c_p, d_p);
    scan_h_kernel<<<dim3(Wn / 32, Cn / 4, Bn), 128, smh>>>(a_p, b_p, c_p, d_p);
    fuse_dw_kernel<<<dim3(3, 3, Bn * Cn), 256>>>(dw_w);
    sgemm_kernel<<<gg, 256>>>(pw_w, p_fd, p_o1);
    gn_stats_kernel<<<dim3(16, Bn), 256>>>(p_o1, gn2_w, gn2_b, p_ss2);
    finalize_kernel<<<(TOTc / 4 + 255) / 256, 256>>>(p_o1, p_ss2, out);
}

// round 6
// speedup vs baseline: 1.4555x; 1.4555x over previous
#include <cuda_runtime.h>
#include <cstdint>

#define Bn 16
#define Cn 256
#define Hn 96
#define Wn 96
#define HWc 9216
#define CHWc 2359296   // Cn*HWc
#define TOTc 37748736  // Bn*CHWc
#define BK 16

typedef unsigned long long ull;

// ---------------- scratch ----------------
__device__ float g_xp[TOTc];
__device__ float g_gate[TOTc];
__device__ float g_sw[TOTc];
__device__ float g_sh[TOTc];
__device__ float g_fd[TOTc];
__device__ float g_o1[TOTc];
__device__ float g_ss1[Bn*Cn*2];
__device__ float g_ss2[Bn*Cn*2];

__device__ __forceinline__ float sigmoid_f(float x) { return 1.0f / (1.0f + __expf(-x)); }
__device__ __forceinline__ float silu_f(float x)    { return x / (1.0f + __expf(-x)); }

// packed f32x2 FMA (SASS FFMA2): d.lo += a.lo*b.lo ; d.hi += a.hi*b.hi
__device__ __forceinline__ void ffma2(ull &d, ull a, ull b) {
    asm("fma.rn.f32x2 %0, %1, %2, %0;" : "+l"(d) : "l"(a), "l"(b));
}
__device__ __forceinline__ ull dup2(float v) {
    unsigned u = __float_as_uint(v);
    ull r; asm("mov.b64 %0, {%1, %1};" : "=l"(r) : "r"(u)); return r;
}
__device__ __forceinline__ float2 ull2f2(ull v) {
    unsigned lo, hi; asm("mov.b64 {%0, %1}, %2;" : "=r"(lo), "=r"(hi) : "l"(v));
    return make_float2(__uint_as_float(lo), __uint_as_float(hi));
}

// ---------------- fp32x2 SGEMM: C[m,n] = sum_k A[m,k]*B[k,n], per-batch ----------------
// M=256, N=9216*16, K=256. BM=BN=128, BK=16, 256 threads, 8x8 per thread, double-buffered.
__global__ __launch_bounds__(256, 2) void sgemm_kernel(const float* __restrict__ A,
                                                       const float* __restrict__ Bsrc,
                                                       float* __restrict__ Cd)
{
    __shared__ __align__(16) float As[2][BK][132];
    __shared__ __align__(16) float Bs[2][BK][128];
    const int tid = threadIdx.x;
    const int bnn = blockIdx.x * 128;
    const int bm  = blockIdx.y * 128;
    const int bb  = blockIdx.z;
    const float* Bp = Bsrc + (size_t)bb * CHWc + bnn;
    float*       Cp = Cd   + (size_t)bb * CHWc + (size_t)bm * HWc + bnn;
    const float* Ap = A + bm * Cn;

    const int a_r = tid >> 2;        // 0..63
    const int a_c = (tid & 3) * 4;   // 0..12
    const int b_r = tid >> 5;        // 0..7
    const int b_c = (tid & 31) * 4;
    const int tx = (tid & 15) * 8;
    const int ty = (tid >> 4) * 8;

    ull acc[4][8];
#pragma unroll
    for (int i = 0; i < 4; i++)
#pragma unroll
        for (int j = 0; j < 8; j++) acc[i][j] = 0ull;

    float4 sa0 = *(const float4*)(Ap + a_r * Cn + a_c);
    float4 sa1 = *(const float4*)(Ap + (a_r + 64) * Cn + a_c);
    float4 sb0 = *(const float4*)(Bp + (size_t)b_r * HWc + b_c);
    float4 sb1 = *(const float4*)(Bp + (size_t)(b_r + 8) * HWc + b_c);

    As[0][a_c+0][a_r] = sa0.x; As[0][a_c+1][a_r] = sa0.y; As[0][a_c+2][a_r] = sa0.z; As[0][a_c+3][a_r] = sa0.w;
    As[0][a_c+0][a_r+64] = sa1.x; As[0][a_c+1][a_r+64] = sa1.y; As[0][a_c+2][a_r+64] = sa1.z; As[0][a_c+3][a_r+64] = sa1.w;
    *(float4*)&Bs[0][b_r][b_c] = sb0;
    *(float4*)&Bs[0][b_r+8][b_c] = sb1;
    __syncthreads();

    int buf = 0;
    for (int kt = 0; kt < Cn / BK; kt++) {
        if (kt < Cn / BK - 1) {
            const int k0 = (kt + 1) * BK;
            sa0 = *(const float4*)(Ap + a_r * Cn + k0 + a_c);
            sa1 = *(const float4*)(Ap + (a_r + 64) * Cn + k0 + a_c);
            sb0 = *(const float4*)(Bp + (size_t)(k0 + b_r) * HWc + b_c);
            sb1 = *(const float4*)(Bp + (size_t)(k0 + b_r + 8) * HWc + b_c);
        }
#pragma unroll
        for (int kk = 0; kk < BK; kk++) {
            ulonglong2 a01 = *(const ulonglong2*)&As[buf][kk][ty];
            ulonglong2 a23 = *(const ulonglong2*)&As[buf][kk][ty + 4];
            float4 bv0 = *(const float4*)&Bs[buf][kk][tx];
            float4 bv1 = *(const float4*)&Bs[buf][kk][tx + 4];
            ull aa0 = a01.x, aa1 = a01.y, aa2 = a23.x, aa3 = a23.y;
            ull w0 = dup2(bv0.x), w1 = dup2(bv0.y), w2 = dup2(bv0.z), w3 = dup2(bv0.w);
            ull w4 = dup2(bv1.x), w5 = dup2(bv1.y), w6 = dup2(bv1.z), w7 = dup2(bv1.w);
            ffma2(acc[0][0], aa0, w0); ffma2(acc[0][1], aa0, w1); ffma2(acc[0][2], aa0, w2); ffma2(acc[0][3], aa0, w3);
            ffma2(acc[0][4], aa0, w4); ffma2(acc[0][5], aa0, w5); ffma2(acc[0][6], aa0, w6); ffma2(acc[0][7], aa0, w7);
            ffma2(acc[1][0], aa1, w0); ffma2(acc[1][1], aa1, w1); ffma2(acc[1][2], aa1, w2); ffma2(acc[1][3], aa1, w3);
            ffma2(acc[1][4], aa1, w4); ffma2(acc[1][5], aa1, w5); ffma2(acc[1][6], aa1, w6); ffma2(acc[1][7], aa1, w7);
            ffma2(acc[2][0], aa2, w0); ffma2(acc[2][1], aa2, w1); ffma2(acc[2][2], aa2, w2); ffma2(acc[2][3], aa2, w3);
            ffma2(acc[2][4], aa2, w4); ffma2(acc[2][5], aa2, w5); ffma2(acc[2][6], aa2, w6); ffma2(acc[2][7], aa2, w7);
            ffma2(acc[3][0], aa3, w0); ffma2(acc[3][1], aa3, w1); ffma2(acc[3][2], aa3, w2); ffma2(acc[3][3], aa3, w3);
            ffma2(acc[3][4], aa3, w4); ffma2(acc[3][5], aa3, w5); ffma2(acc[3][6], aa3, w6); ffma2(acc[3][7], aa3, w7);
        }
        if (kt < Cn / BK - 1) {
            buf ^= 1;
            As[buf][a_c+0][a_r] = sa0.x; As[buf][a_c+1][a_r] = sa0.y; As[buf][a_c+2][a_r] = sa0.z; As[buf][a_c+3][a_r] = sa0.w;
            As[buf][a_c+0][a_r+64] = sa1.x; As[buf][a_c+1][a_r+64] = sa1.y; As[buf][a_c+2][a_r+64] = sa1.z; As[buf][a_c+3][a_r+64] = sa1.w;
            *(float4*)&Bs[buf][b_r][b_c] = sb0;
            *(float4*)&Bs[buf][b_r+8][b_c] = sb1;
            __syncthreads();
        }
    }
#pragma unroll
    for (int i2 = 0; i2 < 4; i2++) {
        float2 c0 = ull2f2(acc[i2][0]), c1 = ull2f2(acc[i2][1]), c2 = ull2f2(acc[i2][2]), c3 = ull2f2(acc[i2][3]);
        float2 c4 = ull2f2(acc[i2][4]), c5 = ull2f2(acc[i2][5]), c6 = ull2f2(acc[i2][6]), c7 = ull2f2(acc[i2][7]);
        const int r0 = ty + 2 * i2;
        *(float4*)(Cp + (size_t)r0 * HWc + tx)       = make_float4(c0.x, c1.x, c2.x, c3.x);
        *(float4*)(Cp + (size_t)r0 * HWc + tx + 4)   = make_float4(c4.x, c5.x, c6.x, c7.x);
        *(float4*)(Cp + (size_t)(r0+1) * HWc + tx)     = make_float4(c0.y, c1.y, c2.y, c3.y);
        *(float4*)(Cp + (size_t)(r0+1) * HWc + tx + 4) = make_float4(c4.y, c5.y, c6.y, c7.y);
    }
}

// ---------------- gate GEMM: B = silu(affine(g_xp)), epilogue sigmoid(+bias) ----------------
__global__ __launch_bounds__(256, 2) void gemm_gate_kernel(const float* __restrict__ A,
                                                           const float* __restrict__ gate_b)
{
    __shared__ __align__(16) float As[2][BK][132];
    __shared__ __align__(16) float Bs[2][BK][128];
    const int tid = threadIdx.x;
    const int bnn = blockIdx.x * 128;
    const int bm  = blockIdx.y * 128;
    const int bb  = blockIdx.z;
    const float* Bp = g_xp   + (size_t)bb * CHWc + bnn;
    float*       Cp = g_gate + (size_t)bb * CHWc + (size_t)bm * HWc + bnn;
    const float* Ap = A + bm * Cn;

    const int a_r = tid >> 2;
    const int a_c = (tid & 3) * 4;
    const int b_r = tid >> 5;
    const int b_c = (tid & 31) * 4;
    const int tx = (tid & 15) * 8;
    const int ty = (tid >> 4) * 8;

    ull acc[4][8];
#pragma unroll
    for (int i = 0; i < 4; i++)
#pragma unroll
        for (int j = 0; j < 8; j++) acc[i][j] = 0ull;

    float4 sa0 = *(const float4*)(Ap + a_r * Cn + a_c);
    float4 sa1 = *(const float4*)(Ap + (a_r + 64) * Cn + a_c);
    float4 sb0 = *(const float4*)(Bp + (size_t)b_r * HWc + b_c);
    float4 sb1 = *(const float4*)(Bp + (size_t)(b_r + 8) * HWc + b_c);
    {
        float2 s0 = *(const float2*)&g_ss1[(bb * Cn + b_r) * 2];
        float2 s1 = *(const float2*)&g_ss1[(bb * Cn + b_r + 8) * 2];
        sb0.x = silu_f(fmaf(sb0.x, s0.x, s0.y)); sb0.y = silu_f(fmaf(sb0.y, s0.x, s0.y));
        sb0.z = silu_f(fmaf(sb0.z, s0.x, s0.y)); sb0.w = silu_f(fmaf(sb0.w, s0.x, s0.y));
        sb1.x = silu_f(fmaf(sb1.x, s1.x, s1.y)); sb1.y = silu_f(fmaf(sb1.y, s1.x, s1.y));
        sb1.z = silu_f(fmaf(sb1.z, s1.x, s1.y)); sb1.w = silu_f(fmaf(sb1.w, s1.x, s1.y));
    }
    As[0][a_c+0][a_r] = sa0.x; As[0][a_c+1][a_r] = sa0.y; As[0][a_c+2][a_r] = sa0.z; As[0][a_c+3][a_r] = sa0.w;
    As[0][a_c+0][a_r+64] = sa1.x; As[0][a_c+1][a_r+64] = sa1.y; As[0][a_c+2][a_r+64] = sa1.z; As[0][a_c+3][a_r+64] = sa1.w;
    *(float4*)&Bs[0][b_r][b_c] = sb0;
    *(float4*)&Bs[0][b_r+8][b_c] = sb1;
    __syncthreads();

    int buf = 0;
    for (int kt = 0; kt < Cn / BK; kt++) {
        if (kt < Cn / BK - 1) {
            const int k0 = (kt + 1) * BK;
            sa0 = *(const float4*)(Ap + a_r * Cn + k0 + a_c);
            sa1 = *(const float4*)(Ap + (a_r + 64) * Cn + k0 + a_c);
            sb0 = *(const float4*)(Bp + (size_t)(k0 + b_r) * HWc + b_c);
            sb1 = *(const float4*)(Bp + (size_t)(k0 + b_r + 8) * HWc + b_c);
            float2 s0 = *(const float2*)&g_ss1[(bb * Cn + k0 + b_r) * 2];
            float2 s1 = *(const float2*)&g_ss1[(bb * Cn + k0 + b_r + 8) * 2];
            sb0.x = silu_f(fmaf(sb0.x, s0.x, s0.y)); sb0.y = silu_f(fmaf(sb0.y, s0.x, s0.y));
            sb0.z = silu_f(fmaf(sb0.z, s0.x, s0.y)); sb0.w = silu_f(fmaf(sb0.w, s0.x, s0.y));
            sb1.x = silu_f(fmaf(sb1.x, s1.x, s1.y)); sb1.y = silu_f(fmaf(sb1.y, s1.x, s1.y));
            sb1.z = silu_f(fmaf(sb1.z, s1.x, s1.y)); sb1.w = silu_f(fmaf(sb1.w, s1.x, s1.y));
        }
#pragma unroll
        for (int kk = 0; kk < BK; kk++) {
            ulonglong2 a01 = *(const ulonglong2*)&As[buf][kk][ty];
            ulonglong2 a23 = *(const ulonglong2*)&As[buf][kk][ty + 4];
            float4 bv0 = *(const float4*)&Bs[buf][kk][tx];
            float4 bv1 = *(const float4*)&Bs[buf][kk][tx + 4];
            ull aa0 = a01.x, aa1 = a01.y, aa2 = a23.x, aa3 = a23.y;
            ull w0 = dup2(bv0.x), w1 = dup2(bv0.y), w2 = dup2(bv0.z), w3 = dup2(bv0.w);
            ull w4 = dup2(bv1.x), w5 = dup2(bv1.y), w6 = dup2(bv1.z), w7 = dup2(bv1.w);
            ffma2(acc[0][0], aa0, w0); ffma2(acc[0][1], aa0, w1); ffma2(acc[0][2], aa0, w2); ffma2(acc[0][3], aa0, w3);
            ffma2(acc[0][4], aa0, w4); ffma2(acc[0][5], aa0, w5); ffma2(acc[0][6], aa0, w6); ffma2(acc[0][7], aa0, w7);
            ffma2(acc[1][0], aa1, w0); ffma2(acc[1][1], aa1, w1); ffma2(acc[1][2], aa1, w2); ffma2(acc[1][3], aa1, w3);
            ffma2(acc[1][4], aa1, w4); ffma2(acc[1][5], aa1, w5); ffma2(acc[1][6], aa1, w6); ffma2(acc[1][7], aa1, w7);
            ffma2(acc[2][0], aa2, w0); ffma2(acc[2][1], aa2, w1); ffma2(acc[2][2], aa2, w2); ffma2(acc[2][3], aa2, w3);
            ffma2(acc[2][4], aa2, w4); ffma2(acc[2][5], aa2, w5); ffma2(acc[2][6], aa2, w6); ffma2(acc[2][7], aa2, w7);
            ffma2(acc[3][0], aa3, w0); ffma2(acc[3][1], aa3, w1); ffma2(acc[3][2], aa3, w2); ffma2(acc[3][3], aa3, w3);
            ffma2(acc[3][4], aa3, w4); ffma2(acc[3][5], aa3, w5); ffma2(acc[3][6], aa3, w6); ffma2(acc[3][7], aa3, w7);
        }
        if (kt < Cn / BK - 1) {
            buf ^= 1;
            As[buf][a_c+0][a_r] = sa0.x; As[buf][a_c+1][a_r] = sa0.y; As[buf][a_c+2][a_r] = sa0.z; As[buf][a_c+3][a_r] = sa0.w;
            As[buf][a_c+0][a_r+64] = sa1.x; As[buf][a_c+1][a_r+64] = sa1.y; As[buf][a_c+2][a_r+64] = sa1.z; As[buf][a_c+3][a_r+64] = sa1.w;
            *(float4*)&Bs[buf][b_r][b_c] = sb0;
            *(float4*)&Bs[buf][b_r+8][b_c] = sb1;
            __syncthreads();
        }
    }
#pragma unroll
    for (int i2 = 0; i2 < 4; i2++) {
        float2 c0 = ull2f2(acc[i2][0]), c1 = ull2f2(acc[i2][1]), c2 = ull2f2(acc[i2][2]), c3 = ull2f2(acc[i2][3]);
        float2 c4 = ull2f2(acc[i2][4]), c5 = ull2f2(acc[i2][5]), c6 = ull2f2(acc[i2][6]), c7 = ull2f2(acc[i2][7]);
        const int r0 = ty + 2 * i2;
        const float gb0 = gate_b[bm + r0], gb1 = gate_b[bm + r0 + 1];
        *(float4*)(Cp + (size_t)r0 * HWc + tx) =
            make_float4(sigmoid_f(c0.x+gb0), sigmoid_f(c1.x+gb0), sigmoid_f(c2.x+gb0), sigmoid_f(c3.x+gb0));
        *(float4*)(Cp + (size_t)r0 * HWc + tx + 4) =
            make_float4(sigmoid_f(c4.x+gb0), sigmoid_f(c5.x+gb0), sigmoid_f(c6.x+gb0), sigmoid_f(c7.x+gb0));
        *(float4*)(Cp + (size_t)(r0+1) * HWc + tx) =
            make_float4(sigmoid_f(c0.y+gb1), sigmoid_f(c1.y+gb1), sigmoid_f(c2.y+gb1), sigmoid_f(c3.y+gb1));
        *(float4*)(Cp + (size_t)(r0+1) * HWc + tx + 4) =
            make_float4(sigmoid_f(c4.y+gb1), sigmoid_f(c5.y+gb1), sigmoid_f(c6.y+gb1), sigmoid_f(c7.y+gb1));
    }
}

// ---------------- GroupNorm stats -> per-(b,c) affine ----------------
__global__ __launch_bounds__(256) void gn_stats_kernel(const float* __restrict__ src,
                                                       const float* __restrict__ gamma,
                                                       const float* __restrict__ beta,
                                                       float* __restrict__ ss)
{
    const int g = blockIdx.x, b = blockIdx.y, tid = threadIdx.x;
    const float4* p = (const float4*)(src + (size_t)b * CHWc + (size_t)g * 16 * HWc);
    float s = 0.0f, s2 = 0.0f;
    const int n4 = 16 * HWc / 4;
    for (int i = tid; i < n4; i += 256) {
        float4 v = p[i];
        s  += v.x + v.y + v.z + v.w;
        s2 += v.x * v.x + v.y * v.y + v.z * v.z + v.w * v.w;
    }
#pragma unroll
    for (int off = 16; off > 0; off >>= 1) {
        s  += __shfl_xor_sync(0xffffffffu, s, off);
        s2 += __shfl_xor_sync(0xffffffffu, s2, off);
    }
    __shared__ float ws[8], ws2[8];
    __shared__ float mean_s, rstd_s;
    const int wid = tid >> 5, lane = tid & 31;
    if (lane == 0) { ws[wid] = s; ws2[wid] = s2; }
    __syncthreads();
    if (tid == 0) {
        float ts = 0.0f, ts2 = 0.0f;
        for (int i = 0; i < 8; i++) { ts += ws[i]; ts2 += ws2[i]; }
        const float inv = 1.0f / (16.0f * HWc);
        float mu  = ts * inv;
        float var = ts2 * inv - mu * mu;
        mean_s = mu;
        rstd_s = rsqrtf(var + 1e-5f);
    }
    __syncthreads();
    if (tid < 16) {
        int c = g * 16 + tid;
        float sc = rstd_s * gamma[c];
        ss[(b * Cn + c) * 2 + 0] = sc;
        ss[(b * Cn + c) * 2 + 1] = beta[c] - mean_s * sc;
    }
}

// ---------------- horizontal scans: warp-per-row parallel scan ----------------
// row id r = ((b*Cn+c)*Hn + h); 24 active lanes x 4 elems = 96. No smem, no barriers.
__global__ __launch_bounds__(256) void scan_w_kernel(const float* __restrict__ ap,
                                                     const float* __restrict__ bp,
                                                     const float* __restrict__ cp,
                                                     const float* __restrict__ dp)
{
    const int gw = blockIdx.x * 8 + (threadIdx.x >> 5);
    const int lane = threadIdx.x & 31;
    const int bc = gw / Hn;
    const int c  = bc & (Cn - 1);
    const float2 sc = *(const float2*)&g_ss1[bc * 2];
    const float a0 = sigmoid_f(ap[c]),    b0 = bp[c],    c0 = cp[c],    d0 = dp[c];
    const float a1 = sigmoid_f(ap[Cn+c]), b1 = bp[Cn+c], c1 = cp[Cn+c], d1 = dp[Cn+c];
    const float* xr = g_xp + (size_t)gw * Wn;

    float x0 = 0.f, x1 = 0.f, x2 = 0.f, x3 = 0.f;
    if (lane < 24) {
        float4 v = *(const float4*)(xr + lane * 4);
        x0 = silu_f(fmaf(v.x, sc.x, sc.y));
        x1 = silu_f(fmaf(v.y, sc.x, sc.y));
        x2 = silu_f(fmaf(v.z, sc.x, sc.y));
        x3 = silu_f(fmaf(v.w, sc.x, sc.y));
    }
    // ---- forward: chunk transform H_out = a0^4 * H_in + S
    float a0_4 = (a0 * a0) * (a0 * a0);
    float S = b0 * x0;
    S = fmaf(a0, S, b0 * x1); S = fmaf(a0, S, b0 * x2); S = fmaf(a0, S, b0 * x3);
    float P = a0_4;
#pragma unroll
    for (int off = 1; off < 32; off <<= 1) {
        float Sp = __shfl_up_sync(0xffffffffu, S, off);
        float Pp = __shfl_up_sync(0xffffffffu, P, off);
        if (lane >= off) { S = fmaf(Sp, P, S); P *= Pp; }
    }
    float Hin = __shfl_up_sync(0xffffffffu, S, 1);
    if (lane == 0) Hin = 0.f;
    float hh = Hin;
    hh = fmaf(a0, hh, b0 * x0); float y0 = fmaf(c0, hh, d0 * x0);
    hh = fmaf(a0, hh, b0 * x1); float y1 = fmaf(c0, hh, d0 * x1);
    hh = fmaf(a0, hh, b0 * x2); float y2 = fmaf(c0, hh, d0 * x2);
    hh = fmaf(a0, hh, b0 * x3); float y3 = fmaf(c0, hh, d0 * x3);
    // ---- backward
    float a1_4 = (a1 * a1) * (a1 * a1);
    float S2 = b1 * x3;
    S2 = fmaf(a1, S2, b1 * x2); S2 = fmaf(a1, S2, b1 * x1); S2 = fmaf(a1, S2, b1 * x0);
    float P2 = a1_4;
    if (lane >= 24) { S2 = 0.f; P2 = 1.f; }
#pragma unroll
    for (int off = 1; off < 32; off <<= 1) {
        float Sp = __shfl_down_sync(0xffffffffu, S2, off);
        float Pp = __shfl_down_sync(0xffffffffu, P2, off);
        if (lane + off < 32) { S2 = fmaf(Sp, P2, S2); P2 *= Pp; }
    }
    float Hin2 = __shfl_down_sync(0xffffffffu, S2, 1);
    if (lane == 31) Hin2 = 0.f;
    hh = Hin2;
    hh = fmaf(a1, hh, b1 * x3); y3 += fmaf(c1, hh, d1 * x3);
    hh = fmaf(a1, hh, b1 * x2); y2 += fmaf(c1, hh, d1 * x2);
    hh = fmaf(a1, hh, b1 * x1); y1 += fmaf(c1, hh, d1 * x1);
    hh = fmaf(a1, hh, b1 * x0); y0 += fmaf(c1, hh, d1 * x0);

    if (lane < 24)
        *(float4*)(g_sw + (size_t)gw * Wn + lane * 4) = make_float4(y0, y1, y2, y3);
}

// ---------------- vertical scans: block per (b,c), thread per column ----------------
__global__ __launch_bounds__(96) void scan_h_kernel(const float* __restrict__ ap,
                                                    const float* __restrict__ bp,
                                                    const float* __restrict__ cp,
                                                    const float* __restrict__ dp)
{
    extern __shared__ float sh[];
    float* xin  = sh;         // 9216
    float* ytmp = sh + HWc;   // 9216
    const int bc = blockIdx.x;
    const int c  = bc & (Cn - 1);
    const int tid = threadIdx.x;
    const float2 sc = *(const float2*)&g_ss1[bc * 2];
    const size_t base = (size_t)bc * HWc;

    for (int i = tid; i < HWc; i += 96)
        xin[i] = silu_f(fmaf(g_xp[base + i], sc.x, sc.y));
    __syncthreads();

    const float a2 = sigmoid_f(ap[2*Cn+c]), b2 = bp[2*Cn+c], c2 = cp[2*Cn+c], d2 = dp[2*Cn+c];
    const float a3 = sigmoid_f(ap[3*Cn+c]), b3 = bp[3*Cn+c], c3 = cp[3*Cn+c], d3 = dp[3*Cn+c];
    const int w = tid;
    float hs = 0.f;
#pragma unroll 4
    for (int hhi = Hn - 1; hhi >= 0; hhi--) {
        float xv = xin[hhi * Wn + w];
        hs = fmaf(a3, hs, b3 * xv);
        ytmp[hhi * Wn + w] = fmaf(c3, hs, d3 * xv);
    }
    hs = 0.f;
#pragma unroll 4
    for (int hhi = 0; hhi < Hn; hhi++) {
        float xv = xin[hhi * Wn + w];
        hs = fmaf(a2, hs, b2 * xv);
        g_sh[base + hhi * Wn + w] = fmaf(c2, hs, d2 * xv) + ytmp[hhi * Wn + w];
    }
}

// ---------------- fused = 0.25*(sw+sh)*gate, 3x3 depthwise SAME conv ----------------
__global__ __launch_bounds__(256) void fuse_dw_kernel(const float* __restrict__ dww)
{
    __shared__ float ft[34 * 36];
    const int bc = blockIdx.z;
    const int h0 = blockIdx.y * 32, w0 = blockIdx.x * 32;
    const int c = bc & (Cn - 1);
    const size_t base = (size_t)bc * HWc;
    const int tid = threadIdx.x;

    for (int i = tid; i < 34 * 34; i += 256) {
        int r = i / 34, cc = i - r * 34;
        int gh = h0 - 1 + r, gw = w0 - 1 + cc;
        float v = 0.0f;
        if ((unsigned)gh < (unsigned)Hn && (unsigned)gw < (unsigned)Wn) {
            size_t idx = base + gh * Wn + gw;
            v = 0.25f * (g_sw[idx] + g_sh[idx]) * g_gate[idx];
        }
        ft[r * 36 + cc] = v;
    }
    float kw[9];
#pragma unroll
    for (int j = 0; j < 9; j++) kw[j] = dww[c * 9 + j];
    __syncthreads();

    const int tx = tid & 31, ty0 = tid >> 5;
#pragma unroll
    for (int rr = 0; rr < 4; rr++) {
        int r = ty0 + rr * 8;
        float acc = 0.0f;
#pragma unroll
        for (int i = 0; i < 3; i++)
#pragma unroll
            for (int j = 0; j < 3; j++)
                acc = fmaf(ft[(r + i) * 36 + tx + j], kw[i * 3 + j], acc);
        g_fd[base + (size_t)(h0 + r) * Wn + w0 + tx] = acc;
    }
}

// ---------------- final: silu(affine(o1)) -> out ----------------
__global__ __launch_bounds__(256) void finalize_kernel(const float* __restrict__ src,
                                                       const float* __restrict__ ss,
                                                       float* __restrict__ out)
{
    int i4 = blockIdx.x * 256 + threadIdx.x;
    if (i4 >= TOTc / 4) return;
    int bc = i4 / (HWc / 4);
    float2 sc = *(const float2*)&ss[bc * 2];
    float4 v = ((const float4*)src)[i4];
    v.x = silu_f(fmaf(v.x, sc.x, sc.y));
    v.y = silu_f(fmaf(v.y, sc.x, sc.y));
    v.z = silu_f(fmaf(v.z, sc.x, sc.y));
    v.w = silu_f(fmaf(v.w, sc.x, sc.y));
    ((float4*)out)[i4] = v;
}

// ---------------- launch ----------------
extern "C" void kernel_launch(void* const* d_in, const int* in_sizes, int n_in,
                              void* d_out, int out_size)
{
    const float* x      = (const float*)d_in[0];
    const float* in_w   = (const float*)d_in[1];
    const float* gn1_w  = (const float*)d_in[2];
    const float* gn1_b  = (const float*)d_in[3];
    const float* a_p    = (const float*)d_in[4];
    const float* b_p    = (const float*)d_in[5];
    const float* c_p    = (const float*)d_in[6];
    const float* d_p    = (const float*)d_in[7];
    const float* gate_w = (const float*)d_in[8];
    const float* gate_b = (const float*)d_in[9];
    const float* dw_w   = (const float*)d_in[10];
    const float* pw_w   = (const float*)d_in[11];
    const float* gn2_w  = (const float*)d_in[12];
    const float* gn2_b  = (const float*)d_in[13];
    float* out = (float*)d_out;

    float *p_xp, *p_fd, *p_o1, *p_ss1, *p_ss2;
    cudaGetSymbolAddress((void**)&p_xp,  g_xp);
    cudaGetSymbolAddress((void**)&p_fd,  g_fd);
    cudaGetSymbolAddress((void**)&p_o1,  g_o1);
    cudaGetSymbolAddress((void**)&p_ss1, g_ss1);
    cudaGetSymbolAddress((void**)&p_ss2, g_ss2);

    const int smh = 2 * HWc * 4;  // 73728
    cudaFuncSetAttribute(scan_h_kernel, cudaFuncAttributeMaxDynamicSharedMemorySize, smh);

    dim3 gg(HWc / 128, Cn / 128, Bn);

    sgemm_kernel<<<gg, 256>>>(in_w, x, p_xp);
    gn_stats_kernel<<<dim3(16, Bn), 256>>>(p_xp, gn1_w, gn1_b, p_ss1);
    gemm_gate_kernel<<<gg, 256>>>(gate_w, gate_b);
    scan_w_kernel<<<Bn * Cn * Hn / 8, 256>>>(a_p, b_p, c_p, d_p);
    scan_h_kernel<<<Bn * Cn, 96, smh>>>(a_p, b_p, c_p, d_p);
    fuse_dw_kernel<<<dim3(3, 3, Bn * Cn), 256>>>(dw_w);
    sgemm_kernel<<<gg, 256>>>(pw_w, p_fd, p_o1);
    gn_stats_kernel<<<dim3(16, Bn), 256>>>(p_o1, gn2_w, gn2_b, p_ss2);
    finalize_kernel<<<(TOTc / 4 + 255) / 256, 256>>>(p_o1, p_ss2, out);
}

// round 8
// speedup vs baseline: 1.6290x; 1.1192x over previous
#include <cuda_runtime.h>
#include <cuda_bf16.h>
#include <cstdint>

#define Bn 16
#define Cn 256
#define Hn 96
#define Wn 96
#define HWc 9216
#define CHWc 2359296   // Cn*HWc
#define TOTc 37748736  // Bn*CHWc

// ---------------- scratch ----------------
__device__ float g_xp[TOTc];
__device__ float g_gate[TOTc];
__device__ float g_sw[TOTc];
__device__ float g_sh[TOTc];
__device__ float g_fd[TOTc];
__device__ float g_o1[TOTc];
__device__ float g_ss1[Bn*Cn*2];
__device__ float g_ss2[Bn*Cn*2];
__device__ __nv_bfloat16 g_bth[TOTc];   // B transposed [b][n][k], hi
__device__ __nv_bfloat16 g_btl[TOTc];   // lo
__device__ __nv_bfloat16 g_ahh[Cn*Cn];  // A hi
__device__ __nv_bfloat16 g_all[Cn*Cn];  // A lo

__device__ __forceinline__ float sigmoid_f(float x) { return 1.0f / (1.0f + __expf(-x)); }
__device__ __forceinline__ float silu_f(float x)    { return x / (1.0f + __expf(-x)); }

__device__ __forceinline__ uint32_t smem_u32(const void* p) {
    uint32_t a;
    asm("{ .reg .u64 t; cvta.to.shared.u64 t, %1; cvt.u32.u64 %0, t; }" : "=r"(a) : "l"(p));
    return a;
}
__device__ __forceinline__ void ldsm4(uint32_t &r0, uint32_t &r1, uint32_t &r2, uint32_t &r3, uint32_t addr) {
    asm volatile("ldmatrix.sync.aligned.m8n8.x4.shared.b16 {%0,%1,%2,%3}, [%4];"
                 : "=r"(r0), "=r"(r1), "=r"(r2), "=r"(r3) : "r"(addr));
}
__device__ __forceinline__ void ldsm2(uint32_t &r0, uint32_t &r1, uint32_t addr) {
    asm volatile("ldmatrix.sync.aligned.m8n8.x2.shared.b16 {%0,%1}, [%2];"
                 : "=r"(r0), "=r"(r1) : "r"(addr));
}
__device__ __forceinline__ void mma16816(float* d, const uint32_t* a, const uint32_t* b) {
    asm volatile("mma.sync.aligned.m16n8k16.row.col.f32.bf16.bf16.f32 "
                 "{%0,%1,%2,%3}, {%4,%5,%6,%7}, {%8,%9}, {%0,%1,%2,%3};"
                 : "+f"(d[0]), "+f"(d[1]), "+f"(d[2]), "+f"(d[3])
                 : "r"(a[0]), "r"(a[1]), "r"(a[2]), "r"(a[3]), "r"(b[0]), "r"(b[1]));
}

// ================ conversion kernels ================
__global__ __launch_bounds__(256) void convA_kernel(const float* __restrict__ A,
                                                    __nv_bfloat16* __restrict__ ah,
                                                    __nv_bfloat16* __restrict__ al)
{
    int i = blockIdx.x * 256 + threadIdx.x;
    float v = A[i];
    __nv_bfloat16 h = __float2bfloat16(v);
    ah[i] = h;
    al[i] = __float2bfloat16(v - __bfloat162float(h));
}

// src fp32 [b][K=256][N=9216] -> bh/bl bf16 [b][N=9216][K=256]; mode1: silu(affine) via ss
__global__ __launch_bounds__(256) void convT_kernel(const float* __restrict__ src,
                                                    __nv_bfloat16* __restrict__ bh,
                                                    __nv_bfloat16* __restrict__ bl,
                                                    const float* __restrict__ ss, int mode)
{
    __shared__ float t[32][33];
    const int n0 = blockIdx.x * 32, k0 = blockIdx.y * 32, bb = blockIdx.z;
    const int tx = threadIdx.x, ty = threadIdx.y;
#pragma unroll
    for (int i = 0; i < 4; i++) {
        int k = k0 + ty + 8 * i;
        float v = src[(size_t)bb * CHWc + (size_t)k * HWc + n0 + tx];
        if (mode) {
            float2 sc = *(const float2*)&ss[(bb * Cn + k) * 2];
            v = silu_f(fmaf(v, sc.x, sc.y));
        }
        t[ty + 8 * i][tx] = v;
    }
    __syncthreads();
#pragma unroll
    for (int i = 0; i < 4; i++) {
        int n = n0 + ty + 8 * i;
        float v = t[tx][ty + 8 * i];
        __nv_bfloat16 h = __float2bfloat16(v);
        size_t o = (size_t)bb * CHWc + (size_t)n * Cn + k0 + tx;
        bh[o] = h;
        bl[o] = __float2bfloat16(v - __bfloat162float(h));
    }
}

// ================ bf16 warp-MMA GEMM: C[b][m][n] = sum_k A[m][k]*Bt[b][n][k] ================
// BM=BN=128, BK=32, 256 threads (8 warps 2x4), warp tile 64x32.
// 3 split passes: (Ah,Bh), (Al,Bh), (Ah,Bl) accumulated into one fp32 accumulator.
#define PITCH 40   // bf16 per smem row: 80B stride, conflict-free ldmatrix (5 coprime 8)
#define ABYTES (128 * PITCH * 2)

__global__ __launch_bounds__(256) void gemm_mma_kernel(
    const __nv_bfloat16* __restrict__ Ah, const __nv_bfloat16* __restrict__ Al,
    const __nv_bfloat16* __restrict__ Bh, const __nv_bfloat16* __restrict__ Bl,
    float* __restrict__ Cd, const float* __restrict__ gbias, int mode)
{
    __shared__ __align__(16) __nv_bfloat16 As[2][128 * PITCH];
    __shared__ __align__(16) __nv_bfloat16 Bs[2][128 * PITCH];
    const int tid = threadIdx.x, lane = tid & 31, warp = tid >> 5;
    const int wm = (warp & 1) * 64, wn = (warp >> 1) * 32;
    const int n0 = blockIdx.x * 128, bm = blockIdx.y * 128, bb = blockIdx.z;

    const __nv_bfloat16* Apass[3] = {Ah, Al, Ah};
    const __nv_bfloat16* Bpass[3] = {Bh, Bh, Bl};

    const int lr = tid >> 1;          // 0..127
    const int lc = (tid & 1) * 2;     // chunk base {0,2}
    const uint32_t saA = smem_u32(As);
    const uint32_t saB = smem_u32(Bs);

    float acc[4][4][4];
#pragma unroll
    for (int i = 0; i < 4; i++)
#pragma unroll
        for (int j = 0; j < 4; j++)
#pragma unroll
            for (int k = 0; k < 4; k++) acc[i][j][k] = 0.0f;

    uint4 ra0, ra1, rb0, rb1;
    {
        const __nv_bfloat16* ap = Apass[0] + (size_t)(bm + lr) * 256 + lc * 8;
        ra0 = *(const uint4*)ap; ra1 = *(const uint4*)(ap + 8);
        const __nv_bfloat16* bp = Bpass[0] + ((size_t)bb * HWc + n0 + lr) * 256 + lc * 8;
        rb0 = *(const uint4*)bp; rb1 = *(const uint4*)(bp + 8);
    }
    *(uint4*)&As[0][lr * PITCH + lc * 8]     = ra0;
    *(uint4*)&As[0][lr * PITCH + lc * 8 + 8] = ra1;
    *(uint4*)&Bs[0][lr * PITCH + lc * 8]     = rb0;
    *(uint4*)&Bs[0][lr * PITCH + lc * 8 + 8] = rb1;
    __syncthreads();

    int buf = 0;
    for (int it = 0; it < 24; it++) {
        if (it < 23) {
            const int nx = it + 1, p = nx >> 3, k0 = (nx & 7) * 32;
            const __nv_bfloat16* ap = Apass[p] + (size_t)(bm + lr) * 256 + k0 + lc * 8;
            ra0 = *(const uint4*)ap; ra1 = *(const uint4*)(ap + 8);
            const __nv_bfloat16* bp = Bpass[p] + ((size_t)bb * HWc + n0 + lr) * 256 + k0 + lc * 8;
            rb0 = *(const uint4*)bp; rb1 = *(const uint4*)(bp + 8);
        }
        const uint32_t sa = saA + buf * ABYTES;
        const uint32_t sb = saB + buf * ABYTES;
#pragma unroll
        for (int ks = 0; ks < 2; ks++) {
            uint32_t af[4][4], bf2[4][2];
#pragma unroll
            for (int mt = 0; mt < 4; mt++) {
                uint32_t addr = sa + (uint32_t)(((wm + mt * 16 + (lane & 15)) * PITCH
                                                + ks * 16 + (lane >> 4) * 8) << 1);
                ldsm4(af[mt][0], af[mt][1], af[mt][2], af[mt][3], addr);
            }
#pragma unroll
            for (int nt = 0; nt < 4; nt++) {
                uint32_t addr = sb + (uint32_t)(((wn + nt * 8 + (lane & 7)) * PITCH
                                                + ks * 16 + ((lane >> 3) & 1) * 8) << 1);
                ldsm2(bf2[nt][0], bf2[nt][1], addr);
            }
#pragma unroll
            for (int mt = 0; mt < 4; mt++)
#pragma unroll
                for (int nt = 0; nt < 4; nt++)
                    mma16816(acc[mt][nt], af[mt], bf2[nt]);
        }
        if (it < 23) {
            buf ^= 1;
            *(uint4*)&As[buf][lr * PITCH + lc * 8]     = ra0;
            *(uint4*)&As[buf][lr * PITCH + lc * 8 + 8] = ra1;
            *(uint4*)&Bs[buf][lr * PITCH + lc * 8]     = rb0;
            *(uint4*)&Bs[buf][lr * PITCH + lc * 8 + 8] = rb1;
            __syncthreads();
        }
    }

    // epilogue: fragment d: rows lane/4 (+8), cols 2*(lane%4)+{0,1}
    const int gr = lane >> 2, gc = (lane & 3) * 2;
#pragma unroll
    for (int mt = 0; mt < 4; mt++) {
        const int row0 = bm + wm + mt * 16 + gr;
        float* p0 = Cd + (size_t)bb * CHWc + (size_t)row0 * HWc + n0 + wn;
        float* p1 = p0 + (size_t)8 * HWc;
        if (mode == 0) {
#pragma unroll
            for (int nt = 0; nt < 4; nt++) {
                *(float2*)(p0 + nt * 8 + gc) = make_float2(acc[mt][nt][0], acc[mt][nt][1]);
                *(float2*)(p1 + nt * 8 + gc) = make_float2(acc[mt][nt][2], acc[mt][nt][3]);
            }
        } else {
            const float gb0 = gbias[row0], gb1 = gbias[row0 + 8];
#pragma unroll
            for (int nt = 0; nt < 4; nt++) {
                *(float2*)(p0 + nt * 8 + gc) =
                    make_float2(sigmoid_f(acc[mt][nt][0] + gb0), sigmoid_f(acc[mt][nt][1] + gb0));
                *(float2*)(p1 + nt * 8 + gc) =
                    make_float2(sigmoid_f(acc[mt][nt][2] + gb1), sigmoid_f(acc[mt][nt][3] + gb1));
            }
        }
    }
}

// ---------------- GroupNorm stats -> per-(b,c) affine ----------------
__global__ __launch_bounds__(256) void gn_stats_kernel(const float* __restrict__ src,
                                                       const float* __restrict__ gamma,
                                                       const float* __restrict__ beta,
                                                       float* __restrict__ ss)
{
    const int g = blockIdx.x, b = blockIdx.y, tid = threadIdx.x;
    const float4* p = (const float4*)(src + (size_t)b * CHWc + (size_t)g * 16 * HWc);
    float s = 0.0f, s2 = 0.0f;
    const int n4 = 16 * HWc / 4;
    for (int i = tid; i < n4; i += 256) {
        float4 v = p[i];
        s  += v.x + v.y + v.z + v.w;
        s2 += v.x * v.x + v.y * v.y + v.z * v.z + v.w * v.w;
    }
#pragma unroll
    for (int off = 16; off > 0; off >>= 1) {
        s  += __shfl_xor_sync(0xffffffffu, s, off);
        s2 += __shfl_xor_sync(0xffffffffu, s2, off);
    }
    __shared__ float ws[8], ws2[8];
    __shared__ float mean_s, rstd_s;
    const int wid = tid >> 5, lane = tid & 31;
    if (lane == 0) { ws[wid] = s; ws2[wid] = s2; }
    __syncthreads();
    if (tid == 0) {
        float ts = 0.0f, ts2 = 0.0f;
        for (int i = 0; i < 8; i++) { ts += ws[i]; ts2 += ws2[i]; }
        const float inv = 1.0f / (16.0f * HWc);
        float mu  = ts * inv;
        float var = ts2 * inv - mu * mu;
        mean_s = mu;
        rstd_s = rsqrtf(var + 1e-5f);
    }
    __syncthreads();
    if (tid < 16) {
        int c = g * 16 + tid;
        float sc = rstd_s * gamma[c];
        ss[(b * Cn + c) * 2 + 0] = sc;
        ss[(b * Cn + c) * 2 + 1] = beta[c] - mean_s * sc;
    }
}

// ---------------- horizontal scans: warp-per-row parallel scan ----------------
__global__ __launch_bounds__(256) void scan_w_kernel(const float* __restrict__ ap,
                                                     const float* __restrict__ bp,
                                                     const float* __restrict__ cp,
                                                     const float* __restrict__ dp)
{
    const int gw = blockIdx.x * 8 + (threadIdx.x >> 5);
    const int lane = threadIdx.x & 31;
    const int bc = gw / Hn;
    const int c  = bc & (Cn - 1);
    const float2 sc = *(const float2*)&g_ss1[bc * 2];
    const float a0 = sigmoid_f(ap[c]),    b0 = bp[c],    c0 = cp[c],    d0 = dp[c];
    const float a1 = sigmoid_f(ap[Cn+c]), b1 = bp[Cn+c], c1 = cp[Cn+c], d1 = dp[Cn+c];
    const float* xr = g_xp + (size_t)gw * Wn;

    float x0 = 0.f, x1 = 0.f, x2 = 0.f, x3 = 0.f;
    if (lane < 24) {
        float4 v = *(const float4*)(xr + lane * 4);
        x0 = silu_f(fmaf(v.x, sc.x, sc.y));
        x1 = silu_f(fmaf(v.y, sc.x, sc.y));
        x2 = silu_f(fmaf(v.z, sc.x, sc.y));
        x3 = silu_f(fmaf(v.w, sc.x, sc.y));
    }
    float a0_4 = (a0 * a0) * (a0 * a0);
    float S = b0 * x0;
    S = fmaf(a0, S, b0 * x1); S = fmaf(a0, S, b0 * x2); S = fmaf(a0, S, b0 * x3);
    float P = a0_4;
#pragma unroll
    for (int off = 1; off < 32; off <<= 1) {
        float Sp = __shfl_up_sync(0xffffffffu, S, off);
        float Pp = __shfl_up_sync(0xffffffffu, P, off);
        if (lane >= off) { S = fmaf(Sp, P, S); P *= Pp; }
    }
    float Hin = __shfl_up_sync(0xffffffffu, S, 1);
    if (lane == 0) Hin = 0.f;
    float hh = Hin;
    hh = fmaf(a0, hh, b0 * x0); float y0 = fmaf(c0, hh, d0 * x0);
    hh = fmaf(a0, hh, b0 * x1); float y1 = fmaf(c0, hh, d0 * x1);
    hh = fmaf(a0, hh, b0 * x2); float y2 = fmaf(c0, hh, d0 * x2);
    hh = fmaf(a0, hh, b0 * x3); float y3 = fmaf(c0, hh, d0 * x3);
    float a1_4 = (a1 * a1) * (a1 * a1);
    float S2 = b1 * x3;
    S2 = fmaf(a1, S2, b1 * x2); S2 = fmaf(a1, S2, b1 * x1); S2 = fmaf(a1, S2, b1 * x0);
    float P2 = a1_4;
    if (lane >= 24) { S2 = 0.f; P2 = 1.f; }
#pragma unroll
    for (int off = 1; off < 32; off <<= 1) {
        float Sp = __shfl_down_sync(0xffffffffu, S2, off);
        float Pp = __shfl_down_sync(0xffffffffu, P2, off);
        if (lane + off < 32) { S2 = fmaf(Sp, P2, S2); P2 *= Pp; }
    }
    float Hin2 = __shfl_down_sync(0xffffffffu, S2, 1);
    if (lane == 31) Hin2 = 0.f;
    hh = Hin2;
    hh = fmaf(a1, hh, b1 * x3); y3 += fmaf(c1, hh, d1 * x3);
    hh = fmaf(a1, hh, b1 * x2); y2 += fmaf(c1, hh, d1 * x2);
    hh = fmaf(a1, hh, b1 * x1); y1 += fmaf(c1, hh, d1 * x1);
    hh = fmaf(a1, hh, b1 * x0); y0 += fmaf(c1, hh, d1 * x0);

    if (lane < 24)
        *(float4*)(g_sw + (size_t)gw * Wn + lane * 4) = make_float4(y0, y1, y2, y3);
}

// ---------------- vertical scans: block per (b,c), thread per column ----------------
__global__ __launch_bounds__(96) void scan_h_kernel(const float* __restrict__ ap,
                                                    const float* __restrict__ bp,
                                                    const float* __restrict__ cp,
                                                    const float* __restrict__ dp)
{
    extern __shared__ float sh[];
    float* xin  = sh;
    float* ytmp = sh + HWc;
    const int bc = blockIdx.x;
    const int c  = bc & (Cn - 1);
    const int tid = threadIdx.x;
    const float2 sc = *(const float2*)&g_ss1[bc * 2];
    const size_t base = (size_t)bc * HWc;

    for (int i = tid; i < HWc; i += 96)
        xin[i] = silu_f(fmaf(g_xp[base + i], sc.x, sc.y));
    __syncthreads();

    const float a2 = sigmoid_f(ap[2*Cn+c]), b2 = bp[2*Cn+c], c2 = cp[2*Cn+c], d2 = dp[2*Cn+c];
    const float a3 = sigmoid_f(ap[3*Cn+c]), b3 = bp[3*Cn+c], c3 = cp[3*Cn+c], d3 = dp[3*Cn+c];
    const int w = tid;
    float hs = 0.f;
#pragma unroll 4
    for (int hhi = Hn - 1; hhi >= 0; hhi--) {
        float xv = xin[hhi * Wn + w];
        hs = fmaf(a3, hs, b3 * xv);
        ytmp[hhi * Wn + w] = fmaf(c3, hs, d3 * xv);
    }
    hs = 0.f;
#pragma unroll 4
    for (int hhi = 0; hhi < Hn; hhi++) {
        float xv = xin[hhi * Wn + w];
        hs = fmaf(a2, hs, b2 * xv);
        g_sh[base + hhi * Wn + w] = fmaf(c2, hs, d2 * xv) + ytmp[hhi * Wn + w];
    }
}

// ---------------- fused = 0.25*(sw+sh)*gate, 3x3 depthwise SAME conv ----------------
__global__ __launch_bounds__(256) void fuse_dw_kernel(const float* __restrict__ dww)
{
    __shared__ float ft[34 * 36];
    const int bc = blockIdx.z;
    const int h0 = blockIdx.y * 32, w0 = blockIdx.x * 32;
    const int c = bc & (Cn - 1);
    const size_t base = (size_t)bc * HWc;
    const int tid = threadIdx.x;

    for (int i = tid; i < 34 * 34; i += 256) {
        int r = i / 34, cc = i - r * 34;
        int gh = h0 - 1 + r, gw = w0 - 1 + cc;
        float v = 0.0f;
        if ((unsigned)gh < (unsigned)Hn && (unsigned)gw < (unsigned)Wn) {
            size_t idx = base + gh * Wn + gw;
            v = 0.25f * (g_sw[idx] + g_sh[idx]) * g_gate[idx];
        }
        ft[r * 36 + cc] = v;
    }
    float kw[9];
#pragma unroll
    for (int j = 0; j < 9; j++) kw[j] = dww[c * 9 + j];
    __syncthreads();

    const int tx = tid & 31, ty0 = tid >> 5;
#pragma unroll
    for (int rr = 0; rr < 4; rr++) {
        int r = ty0 + rr * 8;
        float acc = 0.0f;
#pragma unroll
        for (int i = 0; i < 3; i++)
#pragma unroll
            for (int j = 0; j < 3; j++)
                acc = fmaf(ft[(r + i) * 36 + tx + j], kw[i * 3 + j], acc);
        g_fd[base + (size_t)(h0 + r) * Wn + w0 + tx] = acc;
    }
}

// ---------------- final: silu(affine(o1)) -> out ----------------
__global__ __launch_bounds__(256) void finalize_kernel(const float* __restrict__ src,
                                                       const float* __restrict__ ss,
                                                       float* __restrict__ out)
{
    int i4 = blockIdx.x * 256 + threadIdx.x;
    if (i4 >= TOTc / 4) return;
    int bc = i4 / (HWc / 4);
    float2 sc = *(const float2*)&ss[bc * 2];
    float4 v = ((const float4*)src)[i4];
    v.x = silu_f(fmaf(v.x, sc.x, sc.y));
    v.y = silu_f(fmaf(v.y, sc.x, sc.y));
    v.z = silu_f(fmaf(v.z, sc.x, sc.y));
    v.w = silu_f(fmaf(v.w, sc.x, sc.y));
    ((float4*)out)[i4] = v;
}

// ---------------- launch ----------------
extern "C" void kernel_launch(void* const* d_in, const int* in_sizes, int n_in,
                              void* d_out, int out_size)
{
    const float* x      = (const float*)d_in[0];
    const float* in_w   = (const float*)d_in[1];
    const float* gn1_w  = (const float*)d_in[2];
    const float* gn1_b  = (const float*)d_in[3];
    const float* a_p    = (const float*)d_in[4];
    const float* b_p    = (const float*)d_in[5];
    const float* c_p    = (const float*)d_in[6];
    const float* d_p    = (const float*)d_in[7];
    const float* gate_w = (const float*)d_in[8];
    const float* gate_b = (const float*)d_in[9];
    const float* dw_w   = (const float*)d_in[10];
    const float* pw_w   = (const float*)d_in[11];
    const float* gn2_w  = (const float*)d_in[12];
    const float* gn2_b  = (const float*)d_in[13];
    float* out = (float*)d_out;

    float *p_xp, *p_gate, *p_fd, *p_o1, *p_ss1, *p_ss2;
    __nv_bfloat16 *p_bth, *p_btl, *p_ah, *p_al;
    cudaGetSymbolAddress((void**)&p_xp,   g_xp);
    cudaGetSymbolAddress((void**)&p_gate, g_gate);
    cudaGetSymbolAddress((void**)&p_fd,   g_fd);
    cudaGetSymbolAddress((void**)&p_o1,   g_o1);
    cudaGetSymbolAddress((void**)&p_ss1,  g_ss1);
    cudaGetSymbolAddress((void**)&p_ss2,  g_ss2);
    cudaGetSymbolAddress((void**)&p_bth,  g_bth);
    cudaGetSymbolAddress((void**)&p_btl,  g_btl);
    cudaGetSymbolAddress((void**)&p_ah,   g_ahh);
    cudaGetSymbolAddress((void**)&p_al,   g_all);

    const int smh = 2 * HWc * 4;
    cudaFuncSetAttribute(scan_h_kernel, cudaFuncAttributeMaxDynamicSharedMemorySize, smh);

    dim3 gcv(HWc / 32, Cn / 32, Bn);
    dim3 bcv(32, 8);
    dim3 gmm(HWc / 128, Cn / 128, Bn);

    // GEMM1: xp = in_w @ x
    convT_kernel<<<gcv, bcv>>>(x, p_bth, p_btl, p_ss1, 0);
    convA_kernel<<<Cn * Cn / 256, 256>>>(in_w, p_ah, p_al);
    gemm_mma_kernel<<<gmm, 256>>>(p_ah, p_al, p_bth, p_btl, p_xp, gate_b, 0);
    gn_stats_kernel<<<dim3(16, Bn), 256>>>(p_xp, gn1_w, gn1_b, p_ss1);

    // gate GEMM: gate = sigmoid(gate_w @ silu(affine(xp)) + b)
    convT_kernel<<<gcv, bcv>>>(p_xp, p_bth, p_btl, p_ss1, 1);
    convA_kernel<<<Cn * Cn / 256, 256>>>(gate_w, p_ah, p_al);
    gemm_mma_kernel<<<gmm, 256>>>(p_ah, p_al, p_bth, p_btl, p_gate, gate_b, 1);

    // scans + fuse + depthwise
    scan_w_kernel<<<Bn * Cn * Hn / 8, 256>>>(a_p, b_p, c_p, d_p);
    scan_h_kernel<<<Bn * Cn, 96, smh>>>(a_p, b_p, c_p, d_p);
    fuse_dw_kernel<<<dim3(3, 3, Bn * Cn), 256>>>(dw_w);

    // GEMM3: o1 = pw_w @ fd
    convT_kernel<<<gcv, bcv>>>(p_fd, p_bth, p_btl, p_ss1, 0);
    convA_kernel<<<Cn * Cn / 256, 256>>>(pw_w, p_ah, p_al);
    gemm_mma_kernel<<<gmm, 256>>>(p_ah, p_al, p_bth, p_btl, p_o1, gate_b, 0);

    gn_stats_kernel<<<dim3(16, Bn), 256>>>(p_o1, gn2_w, gn2_b, p_ss2);
    finalize_kernel<<<(TOTc / 4 + 255) / 256, 256>>>(p_o1, p_ss2, out);
}